// round 2
// baseline (speedup 1.0000x reference)
#include <cuda_runtime.h>
#include <cuda_bf16.h>

// add_ResnetBlock_77360950935559
//
// Mathematical reduction of the reference:
//   _adder2d(x, w) = -sum |patch - w|  <= 0 at every output position
//   => relu(_adder2d(x, w1)) == 0  (equality to 0 in the pre-relu value would
//      require an exact 576-term patch/weight match; never for these inputs)
//   => second layer sees all zeros: relu(-sum|w2|) == 0
//   => output = 0.1 * 0 + identity = x   (bit-exact)
//
// Kernel: copy d_in[0] (x: 4*64*40*40 = 409600 fp32 = 1.6 MB) into d_out.
// Vectorized float4 main path; defined scalar-tail kernel for generality.

__global__ void identity_copy_f4(const float4* __restrict__ in,
                                 float4* __restrict__ out, int n4) {
    int i = blockIdx.x * blockDim.x + threadIdx.x;
    if (i < n4) {
        out[i] = in[i];
    }
}

__global__ void identity_copy_tail(const float* __restrict__ in,
                                   float* __restrict__ out,
                                   int start, int n) {
    int i = start + blockIdx.x * blockDim.x + threadIdx.x;
    if (i < n) {
        out[i] = in[i];
    }
}

extern "C" void kernel_launch(void* const* d_in, const int* in_sizes, int n_in,
                              void* d_out, int out_size) {
    const float* x = (const float*)d_in[0];
    float* out = (float*)d_out;

    int n = out_size;            // 409600 floats expected
    int n4 = n >> 2;             // 102400 float4
    int tail = n & 3;            // 0 for this problem

    if (n4 > 0) {
        const int threads = 256;
        int blocks = (n4 + threads - 1) / threads;   // 400 CTAs
        identity_copy_f4<<<blocks, threads>>>((const float4*)x, (float4*)out, n4);
    }
    if (tail > 0) {
        identity_copy_tail<<<1, 32>>>(x, out, n4 << 2, n);
    }
}

// round 3
// speedup vs baseline: 1.0052x; 1.0052x over previous
#include <cuda_runtime.h>
#include <cuda_bf16.h>

// add_ResnetBlock_77360950935559
//
// Mathematical reduction of the reference (verified bit-exact in R2,
// rel_err = 0.0):
//   _adder2d(x, w) = -sum |patch - w|  <= 0 at every output position
//   => relu(_adder2d(x, w1)) == 0
//   => second layer sees all zeros: relu(-sum|w2|) == 0
//   => output = 0.1 * 0 + identity = x   (bit-exact copy of input)
//
// R2 ncu: copy kernel was latency-bound (MLP_p1=1, HBM 4.6%, issue 4.1%).
// R3 change: 4 front-batched independent float4 loads per thread (MLP=4),
// grid 400 -> 100 CTAs. n4 = 102400 = 100 * 256 * 4 exactly.

__global__ void identity_copy_f4x4(const float4* __restrict__ in,
                                   float4* __restrict__ out, int n4) {
    const int stride = gridDim.x * blockDim.x;
    int i = blockIdx.x * blockDim.x + threadIdx.x;

    // Fast path: 4 elements, fully in range (always true for this problem's
    // exact launch geometry). Loads are issued back-to-back (independent)
    // before any store, so the DRAM latency of all 4 overlaps.
    if (i + 3 * stride < n4) {
        float4 a = in[i];
        float4 b = in[i + stride];
        float4 c = in[i + 2 * stride];
        float4 d = in[i + 3 * stride];
        out[i]              = a;
        out[i + stride]     = b;
        out[i + 2 * stride] = c;
        out[i + 3 * stride] = d;
    } else {
        // Generic tail (not taken for n4 = 102400 with this grid).
        for (; i < n4; i += stride) {
            out[i] = in[i];
        }
    }
}

__global__ void identity_copy_tail(const float* __restrict__ in,
                                   float* __restrict__ out,
                                   int start, int n) {
    int i = start + blockIdx.x * blockDim.x + threadIdx.x;
    if (i < n) {
        out[i] = in[i];
    }
}

extern "C" void kernel_launch(void* const* d_in, const int* in_sizes, int n_in,
                              void* d_out, int out_size) {
    const float* x = (const float*)d_in[0];
    float* out = (float*)d_out;

    int n = out_size;            // 409600 floats expected
    int n4 = n >> 2;             // 102400 float4
    int tail = n & 3;            // 0 for this problem

    if (n4 > 0) {
        const int threads = 256;
        const int per_thread = 4;
        int blocks = (n4 + threads * per_thread - 1) / (threads * per_thread); // 100
        identity_copy_f4x4<<<blocks, threads>>>((const float4*)x, (float4*)out, n4);
    }
    if (tail > 0) {
        identity_copy_tail<<<1, 32>>>(x, out, n4 << 2, n);
    }
}

// round 4
// speedup vs baseline: 1.0847x; 1.0791x over previous
#include <cuda_runtime.h>
#include <cuda_bf16.h>

// add_ResnetBlock_77360950935559
//
// Mathematical reduction of the reference (verified bit-exact, rel_err=0.0
// in R2 and R3):
//   _adder2d(x, w) = -sum |patch - w|  <= 0 at every output position
//   => relu(_adder2d(x, w1)) == 0
//   => second layer sees all zeros: relu(-sum|w2|) == 0
//   => output = 0.1 * 0 + identity = x   (bit-exact copy of input)
//
// R2 (400 CTAs, MLP=1) and R3 (100 CTAs, MLP=4) both measured 6.1 us wall /
// ~4.5 us ncu-kernel, invariant to kernel shape -> wall time is dominated by
// graph-replay overhead, and the ncu number reflects cold-cache/low-clock
// profiling conditions, not the timed steady state (L2-resident, ~<1 us).
//
// R4 experiment: replace the SM kernel with a copy-engine memcpy node
// (cudaMemcpyAsync D2D is explicitly graph-capturable per harness rules).
// If a CE node replays cheaper than a kernel node, wall time drops; if
// neutral, the 6.1 us harness floor is confirmed.

__global__ void identity_copy_tail(const float* __restrict__ in,
                                   float* __restrict__ out,
                                   int start, int n) {
    int i = start + blockIdx.x * blockDim.x + threadIdx.x;
    if (i < n) {
        out[i] = in[i];
    }
}

extern "C" void kernel_launch(void* const* d_in, const int* in_sizes, int n_in,
                              void* d_out, int out_size) {
    const float* x = (const float*)d_in[0];
    float* out = (float*)d_out;

    // Single D2D memcpy node: 409600 * 4 bytes = 1.6 MB.
    cudaMemcpyAsync(out, x, (size_t)out_size * sizeof(float),
                    cudaMemcpyDeviceToDevice, 0);
}

// round 5
// speedup vs baseline: 1.1707x; 1.0793x over previous
#include <cuda_runtime.h>
#include <cuda_bf16.h>

// add_ResnetBlock_77360950935559 — CONVERGED (rigor re-bench of best variant)
//
// Mathematical reduction of the reference (bit-exact, rel_err=0.0 in R2-R4):
//   _adder2d(x, w) = -sum |patch - w|  <= 0 at every output position
//   => relu(_adder2d(x, w1)) == 0
//   => second layer sees all zeros: relu(-sum|w2|) == 0
//   => output = 0.1 * 0 + identity = x   (bit-exact copy of input)
//
// Optimization history:
//   R2: float4 SM copy, 400 CTAs          -> 6.14 us
//   R3: float4x4 SM copy (MLP=4), 100 CTAs -> 6.11 us  (shape-invariant =>
//       wall time is graph-replay floor, not data movement)
//   R4: single CE memcpy node              -> 5.66 us  (cheapest node type)
//
// Steady-state copy cost is ~0.3 us (3.2 MB, L2-resident); the remaining
// ~5.4 us is fixed graph submission/replay overhead outside kernel control.
// Multi-stream fork-join was rejected: stream/event creation risks driver-
// side device allocations that the harness mem-checkpoint would fail.
//
// This is a single D2D memcpy node: 409600 * 4 B = 1.6 MB, out <- x.

extern "C" void kernel_launch(void* const* d_in, const int* in_sizes, int n_in,
                              void* d_out, int out_size) {
    const float* x = (const float*)d_in[0];
    float* out = (float*)d_out;

    cudaMemcpyAsync(out, x, (size_t)out_size * sizeof(float),
                    cudaMemcpyDeviceToDevice, 0);
}